// round 14
// baseline (speedup 1.0000x reference)
#include <cuda_runtime.h>
#include <cuda_bf16.h>

// HungarianMatcher cost tensor C[16,900,800], nc=256.
// R10: transposed prob table s_probT[class][row] (stride 34) -> prob gather is
// one LDS.64 per 2 rows (half the gather instrs + half the conflict
// wavefronts). TILE_R=32 -> grid=450 = ONE wave at occ 3; prologue amortized
// 2x. Scalar class mapping keeps softmax stores 2-way conflicted.

constexpr int NC      = 256;
constexpr int TILE_R  = 32;    // query rows per block
constexpr int THREADS = 416;   // 13 warps
constexpr int NWARPS  = THREADS / 32;
constexpr int NT_PER  = 2;     // targets per thread (800 = 400 * 2)
constexpr int PADR    = 34;    // row stride of s_probT (>=TILE_R, 2-way banks)

constexpr float EPS = 1e-7f;

template<int NT>   // NT > 0: compile-time nt; NT == 0: dynamic fallback
__global__ __launch_bounds__(THREADS, 3)
void matcher_cost_kernel(const float* __restrict__ logits,   // [N, NC]
                         const float* __restrict__ pboxes,   // [N, 4]
                         const int*   __restrict__ labels,   // [nt]
                         const float* __restrict__ tboxes,   // [nt, 4]
                         float*       __restrict__ out,      // [N, nt]
                         int n_rows, int nt_dyn)
{
    const int nt = (NT > 0) ? NT : nt_dyn;

    __shared__ float  s_probT[NC][PADR];   // [class][row], ~34KB
    __shared__ float4 s_pred[TILE_R][2];   // {cx,cy,w,h},{x0,y0,x1,y1}

    const int tid  = threadIdx.x;
    const int lane = tid & 31;
    const int warp = tid >> 5;
    const int n0   = blockIdx.x * TILE_R;

    // --- Softmax: warps stride rows; lane owns classes lane+32i (scalar) ---
    for (int rr = warp; rr < TILE_R; rr += NWARPS) {
        const int n = n0 + rr;
        if (n >= n_rows) break;
        const float* lr = logits + (size_t)n * NC;
        float v[8];
        #pragma unroll
        for (int i = 0; i < 8; i++) v[i] = lr[lane + 32 * i];

        float mx = v[0];
        #pragma unroll
        for (int i = 1; i < 8; i++) mx = fmaxf(mx, v[i]);
        #pragma unroll
        for (int o = 16; o > 0; o >>= 1)
            mx = fmaxf(mx, __shfl_xor_sync(0xffffffffu, mx, o));

        float sum = 0.f;
        #pragma unroll
        for (int i = 0; i < 8; i++) { v[i] = __expf(v[i] - mx); sum += v[i]; }
        #pragma unroll
        for (int o = 16; o > 0; o >>= 1)
            sum += __shfl_xor_sync(0xffffffffu, sum, o);
        float inv = __fdividef(1.0f, sum);

        #pragma unroll
        for (int i = 0; i < 8; i++)
            s_probT[lane + 32 * i][rr] = v[i] * inv;   // 2-way bank conflict

        if (lane == 0) {
            float4 pb = reinterpret_cast<const float4*>(pboxes)[n];
            float hw = 0.5f * pb.z, hh = 0.5f * pb.w;
            s_pred[rr][0] = pb;
            s_pred[rr][1] = make_float4(pb.x - hw, pb.y - hh, pb.x + hw, pb.y + hh);
        }
    }
    __syncthreads();

    const int mbase = tid * NT_PER;
    const bool full_tile = (n0 + TILE_R) <= n_rows;   // true: 14400 % 32 == 0

    if (mbase + NT_PER <= nt && full_tile) {
        // --- Fast path: 2 targets in regs; 2-row groups; LDS.64 prob gather ---
        float tcx[NT_PER], tcy[NT_PER], tw2[NT_PER], th2[NT_PER];
        float tx0[NT_PER], ty0[NT_PER], tx1[NT_PER], ty1[NT_PER], ta[NT_PER];
        const float4* tb4 = reinterpret_cast<const float4*>(tboxes);
        int2 lb = reinterpret_cast<const int2*>(labels)[tid];
        #pragma unroll
        for (int j = 0; j < NT_PER; j++) {
            float4 b = tb4[mbase + j];
            tcx[j] = b.x; tcy[j] = b.y; tw2[j] = b.z; th2[j] = b.w;
            float hw = 0.5f * b.z, hh = 0.5f * b.w;
            tx0[j] = b.x - hw; ty0[j] = b.y - hh;
            tx1[j] = b.x + hw; ty1[j] = b.y + hh;
            ta[j]  = b.z * b.w;
        }
        const float* gA = s_probT[lb.x];
        const float* gB = s_probT[lb.y];
        float* op = out + (size_t)n0 * nt + mbase;

        #pragma unroll 4
        for (int g = 0; g < TILE_R / 2; g++) {
            float2 pA = *reinterpret_cast<const float2*>(gA + 2 * g);  // rows 2g,2g+1
            float2 pB = *reinterpret_cast<const float2*>(gB + 2 * g);
            float pAr[2] = {pA.x, pA.y};
            float pBr[2] = {pB.x, pB.y};

            #pragma unroll
            for (int rr = 0; rr < 2; rr++) {
                const int r = 2 * g + rr;
                const float4 pc = s_pred[r][0];   // broadcast LDS.128
                const float4 px = s_pred[r][1];
                const float  pa = pc.z * pc.w;

                float res0, res1;
                {
                    float l1 = fabsf(pc.x - tcx[0]) + fabsf(pc.y - tcy[0])
                             + fabsf(pc.z - tw2[0]) + fabsf(pc.w - th2[0]);
                    float ix = fminf(px.z, tx1[0]) - fmaxf(px.x, tx0[0]);
                    float iy = fminf(px.w, ty1[0]) - fmaxf(px.y, ty0[0]);
                    float inter = fmaxf(ix, 0.f) * fmaxf(iy, 0.f);
                    float uni   = pa + ta[0] - inter;
                    float cxv = (pc.z + tw2[0]) - ix;
                    float cyv = (pc.w + th2[0]) - iy;
                    float ca  = cxv * cyv;
                    float u = uni + EPS, c = ca + EPS;
                    float num = fmaf(uni - ca, u, inter * c);
                    float giou = __fdividef(num, u * c);
                    res0 = fmaf(-2.f, giou, fmaf(5.f, l1, -pAr[rr]));
                }
                {
                    float l1 = fabsf(pc.x - tcx[1]) + fabsf(pc.y - tcy[1])
                             + fabsf(pc.z - tw2[1]) + fabsf(pc.w - th2[1]);
                    float ix = fminf(px.z, tx1[1]) - fmaxf(px.x, tx0[1]);
                    float iy = fminf(px.w, ty1[1]) - fmaxf(px.y, ty0[1]);
                    float inter = fmaxf(ix, 0.f) * fmaxf(iy, 0.f);
                    float uni   = pa + ta[1] - inter;
                    float cxv = (pc.z + tw2[1]) - ix;
                    float cyv = (pc.w + th2[1]) - iy;
                    float ca  = cxv * cyv;
                    float u = uni + EPS, c = ca + EPS;
                    float num = fmaf(uni - ca, u, inter * c);
                    float giou = __fdividef(num, u * c);
                    res1 = fmaf(-2.f, giou, fmaf(5.f, l1, -pBr[rr]));
                }
                *reinterpret_cast<float2*>(op + (size_t)r * nt) =
                    make_float2(res0, res1);
            }
        }
    } else if (mbase < nt) {
        // generic path (partial tile / odd nt; unused for the bench shape)
        const int rmax = min(TILE_R, n_rows - n0);
        for (int j = 0; j < NT_PER && mbase + j < nt; j++) {
            int m = mbase + j;
            float4 b = reinterpret_cast<const float4*>(tboxes)[m];
            int lbm = labels[m];
            float hw = 0.5f * b.z, hh = 0.5f * b.w;
            float bx0 = b.x - hw, by0 = b.y - hh, bx1 = b.x + hw, by1 = b.y + hh;
            float bar = b.z * b.w;
            for (int r = 0; r < rmax; r++) {
                float4 pc = s_pred[r][0];
                float4 px = s_pred[r][1];
                float  pa = pc.z * pc.w;
                float pp = s_probT[lbm][r];
                float l1 = fabsf(pc.x - b.x) + fabsf(pc.y - b.y)
                         + fabsf(pc.z - b.z) + fabsf(pc.w - b.w);
                float ix = fminf(px.z, bx1) - fmaxf(px.x, bx0);
                float iy = fminf(px.w, by1) - fmaxf(px.y, by0);
                float inter = fmaxf(ix, 0.f) * fmaxf(iy, 0.f);
                float uni = pa + bar - inter;
                float iou = __fdividef(inter, uni + EPS);
                float cxv = fmaxf(px.z, bx1) - fminf(px.x, bx0);
                float cyv = fmaxf(px.w, by1) - fminf(px.y, by0);
                float ca = cxv * cyv;
                float giou = iou - __fdividef(ca - uni, ca + EPS);
                out[(size_t)(n0 + r) * nt + m] = 5.f * l1 - pp - 2.f * giou;
            }
        }
    }
}

extern "C" void kernel_launch(void* const* d_in, const int* in_sizes, int n_in,
                              void* d_out, int out_size)
{
    const float* logits = (const float*)d_in[0];
    const float* pboxes = (const float*)d_in[1];
    const int*   labels = (const int*)  d_in[2];
    const float* tboxes = (const float*)d_in[3];
    float*       out    = (float*)d_out;

    const int n_rows = in_sizes[1] / 4;   // 14400
    const int nt     = in_sizes[2];       // 800

    const int blocks = (n_rows + TILE_R - 1) / TILE_R;   // 450
    if (nt == 800) {
        matcher_cost_kernel<800><<<blocks, THREADS>>>(logits, pboxes, labels,
                                                      tboxes, out, n_rows, nt);
    } else {
        matcher_cost_kernel<0><<<blocks, THREADS>>>(logits, pboxes, labels,
                                                    tboxes, out, n_rows, nt);
    }
}